// round 17
// baseline (speedup 1.0000x reference)
#include <cuda_runtime.h>
#include <cuda_fp16.h>
#include <math.h>
#include <stdint.h>

#define N_NODES   100000
#define N_EDGES   200000
#define EMB       300
#define EMB2      600
#define NUM_LAYER 5
#define NUM_GRAPHS 5000
#define BN_EPS    1e-5f

// ---------------- device scratch (allocation-free) ----------------
__device__ __align__(16) float g_h[N_NODES * EMB];
__device__ __align__(16) float g_agg[N_NODES * EMB];
__device__ __align__(16) float g_t[N_NODES * EMB2];
__device__ __align__(16) float g_tab[9 * EMB];
__device__ float g_stats[2 * EMB];              // [0:EMB) sum(y), [EMB:2EMB) sum(y^2)
__device__ __align__(16) float g_bnco[2 * EMB]; // [0:EMB) scale, [EMB:2EMB) offset
__device__ float g_counts[NUM_GRAPHS];
// CSR by destination (built once per launch; graph constant across layers)
__device__ int g_rowptr[N_NODES + 1];
__device__ int g_fill[N_NODES];
__device__ int g_bsum[1024];
__device__ uint32_t g_esrc[N_EDGES];   // packed (src << 4) | attr_type
// pre-split weights for ALL layers (fp16 hi/lo), zero-padded
// W1: [5][640][320], W2: [5][384][640]
#define W1_LSZ (640 * 320)
#define W2_LSZ (384 * 640)
__device__ __align__(16) __half g_w1h[NUM_LAYER * W1_LSZ];
__device__ __align__(16) __half g_w1l[NUM_LAYER * W1_LSZ];
__device__ __align__(16) __half g_w2h[NUM_LAYER * W2_LSZ];
__device__ __align__(16) __half g_w2l[NUM_LAYER * W2_LSZ];

__device__ __forceinline__ uint32_t smem_u32(const void* p) {
    uint32_t a;
    asm("{ .reg .u64 t; cvta.to.shared.u64 t, %1; cvt.u32.u64 %0, t; }" : "=r"(a) : "l"(p));
    return a;
}
__device__ __forceinline__ float4 f4add(float4 a, float4 b) {
    return make_float4(a.x + b.x, a.y + b.y, a.z + b.z, a.w + b.w);
}
__device__ __forceinline__ float4 bnrelu4(float4 y, float4 s, float4 o) {
    return make_float4(fmaxf(fmaf(y.x, s.x, o.x), 0.f),
                       fmaxf(fmaf(y.y, s.y, o.y), 0.f),
                       fmaxf(fmaf(y.z, s.z, o.z), 0.f),
                       fmaxf(fmaf(y.w, s.w, o.w), 0.f));
}

// ---------------- h0 = x_emb1[x0] + x_emb2[x1] ----------------
__global__ void init_h_kernel(const int* __restrict__ x,
                              const float* __restrict__ e1,
                              const float* __restrict__ e2) {
    int idx = blockIdx.x * blockDim.x + threadIdx.x;
    if (idx >= N_NODES * EMB) return;
    int i = idx / EMB, c = idx - i * EMB;
    int a = x[2 * i], b = x[2 * i + 1];
    g_h[idx] = e1[a * EMB + c] + e2[b * EMB + c];
}

// ------ per-layer prep: BN coeffs (layer l-1), zero stats, eemb table (layer l) ------
// Safe in one kernel: thread c (<EMB) owns stats[c] and stats[EMB+c] exclusively:
// it reads them for bnco, then zeroes them. Other threads only touch g_tab.
__global__ void layer_prep_kernel(const float* __restrict__ e1,
                                  const float* __restrict__ e2,
                                  const float* __restrict__ gamma,
                                  const float* __restrict__ beta,
                                  int l, int doBnco) {
    int idx = blockIdx.x * blockDim.x + threadIdx.x;
    if (idx < EMB) {
        if (doBnco) {
            float mu  = g_stats[idx] * (1.f / N_NODES);
            float var = fmaxf(g_stats[EMB + idx] * (1.f / N_NODES) - mu * mu, 0.f);
            float sc  = rsqrtf(var + BN_EPS) * gamma[(l - 1) * EMB + idx];
            g_bnco[idx]       = sc;
            g_bnco[EMB + idx] = beta[(l - 1) * EMB + idx] - mu * sc;
        }
        g_stats[idx] = 0.f;
        g_stats[EMB + idx] = 0.f;
    }
    if (idx < 9 * EMB) {
        int t = idx / EMB, c = idx - t * EMB;
        int a = t / 3, b = t - a * 3;
        g_tab[idx] = e1[(l * 6 + a) * EMB + c] + e2[(l * 3 + b) * EMB + c];
    }
}

// ================= CSR build (once per launch) =================
__global__ void csr_zero_kernel() {
    int i = blockIdx.x * blockDim.x + threadIdx.x;
    if (i <= N_NODES) g_rowptr[i] = 0;
}
__global__ void csr_count_kernel(const int* __restrict__ ei) {
    int e = blockIdx.x * blockDim.x + threadIdx.x;
    if (e >= N_EDGES) return;
    atomicAdd(&g_rowptr[ei[N_EDGES + e] + 1], 1);
}
__global__ void csr_scan1_kernel(int n) {
    __shared__ int sh[1024];
    int gid = blockIdx.x * 1024 + threadIdx.x;
    int v = (gid < n) ? g_rowptr[gid] : 0;
    sh[threadIdx.x] = v;
    __syncthreads();
    #pragma unroll
    for (int off = 1; off < 1024; off <<= 1) {
        int t = (threadIdx.x >= off) ? sh[threadIdx.x - off] : 0;
        __syncthreads();
        sh[threadIdx.x] += t;
        __syncthreads();
    }
    if (gid < n) g_rowptr[gid] = sh[threadIdx.x];
    if (threadIdx.x == 1023) g_bsum[blockIdx.x] = sh[1023];
}
__global__ void csr_scan2_kernel(int nb) {
    __shared__ int sh[1024];
    int v = (threadIdx.x < nb) ? g_bsum[threadIdx.x] : 0;
    sh[threadIdx.x] = v;
    __syncthreads();
    #pragma unroll
    for (int off = 1; off < 1024; off <<= 1) {
        int t = (threadIdx.x >= off) ? sh[threadIdx.x - off] : 0;
        __syncthreads();
        sh[threadIdx.x] += t;
        __syncthreads();
    }
    if (threadIdx.x < nb) g_bsum[threadIdx.x] = sh[threadIdx.x] - v;
}
__global__ void csr_scan3_kernel(int n) {
    int gid = blockIdx.x * 1024 + threadIdx.x;
    if (gid < n) g_rowptr[gid] += g_bsum[blockIdx.x];
}
__global__ void csr_fill_kernel() {
    int i = blockIdx.x * blockDim.x + threadIdx.x;
    if (i < N_NODES) g_fill[i] = g_rowptr[i];
}
__global__ void csr_place_kernel(const int* __restrict__ ei,
                                 const int* __restrict__ ea) {
    int e = blockIdx.x * blockDim.x + threadIdx.x;
    if (e >= N_EDGES) return;
    int d = ei[N_EDGES + e];
    int pos = atomicAdd(&g_fill[d], 1);
    int t = ea[2 * e] * 3 + ea[2 * e + 1];
    g_esrc[pos] = ((uint32_t)ei[e] << 4) | (uint32_t)t;
}

// ------- gather with optional fused BN+relu on loaded values -------
__global__ __launch_bounds__(256) void gather_kernel(
        const float* __restrict__ src, float* __restrict__ dst, int applyBN) {
    int node = blockIdx.x * 8 + (threadIdx.x >> 5);
    if (node >= N_NODES) return;
    int lane = threadIdx.x & 31;
    int beg = g_rowptr[node], end = g_rowptr[node + 1];
    const int c0 = lane, c1 = lane + 32, c2 = lane + 64;   // c2 valid iff lane < 11

    float4 z = make_float4(0, 0, 0, 0);
    float4 sc0 = z, sc1 = z, sc2 = z, of0 = z, of1 = z, of2 = z;
    if (applyBN) {
        const float4* scp = (const float4*)g_bnco;
        const float4* ofp = (const float4*)(g_bnco + EMB);
        sc0 = scp[c0]; of0 = ofp[c0];
        sc1 = scp[c1]; of1 = ofp[c1];
        if (lane < 11) { sc2 = scp[c2]; of2 = ofp[c2]; }
    }

    const float4* hd = (const float4*)(src + (size_t)node * EMB);
    const float4* t0 = (const float4*)g_tab;

    float4 v0 = hd[c0], v1 = hd[c1], v2 = (lane < 11) ? hd[c2] : z;
    if (applyBN) {
        v0 = bnrelu4(v0, sc0, of0);
        v1 = bnrelu4(v1, sc1, of1);
        if (lane < 11) v2 = bnrelu4(v2, sc2, of2);
    }
    float4 a0 = f4add(v0, t0[c0]);
    float4 a1 = f4add(v1, t0[c1]);
    float4 a2 = (lane < 11) ? f4add(v2, t0[c2]) : z;

    for (int e = beg; e < end; ++e) {
        uint32_t v = g_esrc[e];
        const float4* hs = (const float4*)(src + (size_t)(v >> 4) * EMB);
        const float4* tb = (const float4*)(g_tab + (v & 15u) * EMB);
        float4 w0 = hs[c0], w1 = hs[c1], w2 = (lane < 11) ? hs[c2] : z;
        if (applyBN) {
            w0 = bnrelu4(w0, sc0, of0);
            w1 = bnrelu4(w1, sc1, of1);
            if (lane < 11) w2 = bnrelu4(w2, sc2, of2);
        }
        a0 = f4add(a0, f4add(w0, tb[c0]));
        a1 = f4add(a1, f4add(w1, tb[c1]));
        if (lane < 11) a2 = f4add(a2, f4add(w2, tb[c2]));
    }
    float4* ag = (float4*)(dst + (size_t)node * EMB);
    ag[c0] = a0;
    ag[c1] = a1;
    if (lane < 11) ag[c2] = a2;
}

// ------- weight transpose + fp16 hi/lo split, ALL layers (z = layer) -------
__global__ void transpose_split_all_kernel(const float* __restrict__ W,
                                           __half* __restrict__ Wh,
                                           __half* __restrict__ Wl,
                                           int N, int K, int Npad, int Kpad) {
    __shared__ float tile[32][33];
    int tx = threadIdx.x, ty = threadIdx.y;
    int nb = blockIdx.x * 32, kb = blockIdx.y * 32;
    int lz = blockIdx.z;
    const float* Wsrc = W + (size_t)lz * N * K;
    __half* dh = Wh + (size_t)lz * Npad * Kpad;
    __half* dl = Wl + (size_t)lz * Npad * Kpad;
    #pragma unroll
    for (int j = 0; j < 4; ++j) {
        int gk = kb + ty + j * 8, gn = nb + tx;
        tile[ty + j * 8][tx] = (gk < K && gn < N) ? Wsrc[(size_t)gk * N + gn] : 0.f;
    }
    __syncthreads();
    #pragma unroll
    for (int j = 0; j < 4; ++j) {
        int gn = nb + ty + j * 8, gk = kb + tx;
        if (gn < Npad && gk < Kpad) {
            float v = tile[tx][ty + j * 8];
            __half hi = __float2half_rn(v);
            __half lo = __float2half_rn(v - __half2float(hi));
            dh[(size_t)gn * Kpad + gk] = hi;
            dl[(size_t)gn * Kpad + gk] = lo;
        }
    }
}

// ====== unified 3-term split-fp16 GEMM: 128x64 CTA tile, double-buffered ======
#define KT 32
#define WSTRIDE 20
#define AH_OFF  0
#define AL_OFF  (128 * WSTRIDE)
#define BH_OFF  (256 * WSTRIDE)
#define BL_OFF  (320 * WSTRIDE)
#define STAGEW  (384 * WSTRIDE)
#define GEMM_SMEM (2 * STAGEW * 4)     // 61440 B

__device__ __forceinline__ void mma16f(float* c, const uint32_t* a, const uint32_t* b) {
    asm volatile(
        "mma.sync.aligned.m16n8k16.row.col.f32.f16.f16.f32 "
        "{%0,%1,%2,%3},{%4,%5,%6,%7},{%8,%9},{%0,%1,%2,%3};\n"
        : "+f"(c[0]), "+f"(c[1]), "+f"(c[2]), "+f"(c[3])
        : "r"(a[0]), "r"(a[1]), "r"(a[2]), "r"(a[3]), "r"(b[0]), "r"(b[1]));
}
__device__ __forceinline__ void ldmx4(uint32_t* r, uint32_t addr) {
    asm volatile("ldmatrix.sync.aligned.m8n8.x4.shared.b16 {%0,%1,%2,%3}, [%4];"
        : "=r"(r[0]), "=r"(r[1]), "=r"(r[2]), "=r"(r[3]) : "r"(addr));
}

__device__ __forceinline__ void split4h(float4 f, uint2& hi, uint2& lo) {
    __half h0 = __float2half_rn(f.x), h1 = __float2half_rn(f.y),
           h2 = __float2half_rn(f.z), h3 = __float2half_rn(f.w);
    __half l0 = __float2half_rn(f.x - __half2float(h0)),
           l1 = __float2half_rn(f.y - __half2float(h1)),
           l2 = __float2half_rn(f.z - __half2float(h2)),
           l3 = __float2half_rn(f.w - __half2float(h3));
    __half2 ha = __halves2half2(h0, h1), hb = __halves2half2(h2, h3);
    __half2 la = __halves2half2(l0, l1), lb = __halves2half2(l2, l3);
    hi = make_uint2(*(uint32_t*)&ha, *(uint32_t*)&hb);
    lo = make_uint2(*(uint32_t*)&la, *(uint32_t*)&lb);
}

__global__ __launch_bounds__(256, 2) void gemm_n64_kernel(
        const float* __restrict__ A,
        const __half* __restrict__ Wh,
        const __half* __restrict__ Wl,
        const float* __restrict__ bias, float* __restrict__ C,
        int M, int N, int K, int Kpad, int doRelu, int doStats) {
    extern __shared__ __align__(16) uint32_t sm[];

    const int tid  = threadIdx.x;
    const int lane = tid & 31;
    const int warp = tid >> 5;
    const int g = lane >> 2;
    const int t = lane & 3;
    const int wm = (warp & 3) * 32;
    const int wn = (warp >> 2) * 32;
    const int row0 = blockIdx.y * 128;
    const int col0 = blockIdx.x * 64;

    const uint32_t sb0 = smem_u32(sm);

    const int l8  = lane & 7;
    const int sel = lane >> 3;
    const int a_row  = l8 + ((sel & 1) << 3);
    const int a_koff = ((sel >> 1) << 3) * 2;
    const int b_row  = l8 + ((sel >> 1) << 3);
    const int b_koff = ((sel & 1) << 3) * 2;

    float c[2][4][4] = {};
    float4 ra[4];
    uint4  rb[2];

    const int nk = (K + KT - 1) / KT;

    #pragma unroll
    for (int it = 0; it < 4; ++it) {
        int idx = tid + it * 256;
        int r = idx >> 3, kq = idx & 7;
        int gr = row0 + r, gk = kq * 4;
        ra[it] = (gr < M && gk < K) ? *(const float4*)(A + (size_t)gr * K + gk)
                                    : make_float4(0.f, 0.f, 0.f, 0.f);
    }
    #pragma unroll
    for (int it = 0; it < 2; ++it) {
        int idx = tid + it * 256;
        int term = idx >> 8, rem = idx & 255;
        int r = rem >> 2, q = rem & 3;
        rb[it] = *(const uint4*)((term ? Wl : Wh) + (size_t)(col0 + r) * Kpad + q * 8);
    }
    {
        uint32_t* S = sm;
        #pragma unroll
        for (int it = 0; it < 4; ++it) {
            int idx = tid + it * 256;
            int r = idx >> 3, kq = idx & 7;
            uint2 hi, lo;
            split4h(ra[it], hi, lo);
            *(uint2*)&S[AH_OFF + r * WSTRIDE + kq * 2] = hi;
            *(uint2*)&S[AL_OFF + r * WSTRIDE + kq * 2] = lo;
        }
        #pragma unroll
        for (int it = 0; it < 2; ++it) {
            int idx = tid + it * 256;
            int term = idx >> 8, rem = idx & 255;
            int r = rem >> 2, q = rem & 3;
            *(uint4*)&S[(term ? BL_OFF : BH_OFF) + r * WSTRIDE + q * 4] = rb[it];
        }
    }
    __syncthreads();

    for (int kt = 0; kt < nk; ++kt) {
        const uint32_t sb = sb0 + (kt & 1) * (STAGEW * 4);

        if (kt + 1 < nk) {
            int k0 = (kt + 1) * KT;
            #pragma unroll
            for (int it = 0; it < 4; ++it) {
                int idx = tid + it * 256;
                int r = idx >> 3, kq = idx & 7;
                int gr = row0 + r, gk = k0 + kq * 4;
                ra[it] = (gr < M && gk < K) ? *(const float4*)(A + (size_t)gr * K + gk)
                                            : make_float4(0.f, 0.f, 0.f, 0.f);
            }
            #pragma unroll
            for (int it = 0; it < 2; ++it) {
                int idx = tid + it * 256;
                int term = idx >> 8, rem = idx & 255;
                int r = rem >> 2, q = rem & 3;
                rb[it] = *(const uint4*)((term ? Wl : Wh) +
                         (size_t)(col0 + r) * Kpad + k0 + q * 8);
            }
        }

        const uint32_t sAh = sb + AH_OFF * 4;
        const uint32_t sAl = sb + AL_OFF * 4;
        const uint32_t sBh = sb + BH_OFF * 4;
        const uint32_t sBl = sb + BL_OFF * 4;
        #pragma unroll
        for (int ks = 0; ks < 2; ++ks) {
            const int ka = ks * 32 + a_koff;
            const int kb = ks * 32 + b_koff;
            uint32_t afh[2][4], afl[2][4], bfh[4][2], bfl[4][2];
            #pragma unroll
            for (int i = 0; i < 2; ++i) {
                uint32_t ro = (uint32_t)(wm + i * 16 + a_row) * 80 + ka;
                ldmx4(afh[i], sAh + ro);
                ldmx4(afl[i], sAl + ro);
            }
            #pragma unroll
            for (int j2 = 0; j2 < 2; ++j2) {
                uint32_t ro = (uint32_t)(wn + j2 * 16 + b_row) * 80 + kb;
                uint32_t r[4];
                ldmx4(r, sBh + ro);
                bfh[2 * j2][0] = r[0]; bfh[2 * j2][1] = r[1];
                bfh[2 * j2 + 1][0] = r[2]; bfh[2 * j2 + 1][1] = r[3];
                ldmx4(r, sBl + ro);
                bfl[2 * j2][0] = r[0]; bfl[2 * j2][1] = r[1];
                bfl[2 * j2 + 1][0] = r[2]; bfl[2 * j2 + 1][1] = r[3];
            }
            #pragma unroll
            for (int i = 0; i < 2; ++i)
                #pragma unroll
                for (int j = 0; j < 4; ++j) {
                    mma16f(c[i][j], afl[i], bfh[j]);
                    mma16f(c[i][j], afh[i], bfl[j]);
                    mma16f(c[i][j], afh[i], bfh[j]);
                }
        }

        if (kt + 1 < nk) {
            uint32_t* S = sm + ((kt + 1) & 1) * STAGEW;
            #pragma unroll
            for (int it = 0; it < 4; ++it) {
                int idx = tid + it * 256;
                int r = idx >> 3, kq = idx & 7;
                uint2 hi, lo;
                split4h(ra[it], hi, lo);
                *(uint2*)&S[AH_OFF + r * WSTRIDE + kq * 2] = hi;
                *(uint2*)&S[AL_OFF + r * WSTRIDE + kq * 2] = lo;
            }
            #pragma unroll
            for (int it = 0; it < 2; ++it) {
                int idx = tid + it * 256;
                int term = idx >> 8, rem = idx & 255;
                int r = rem >> 2, q = rem & 3;
                *(uint4*)&S[(term ? BL_OFF : BH_OFF) + r * WSTRIDE + q * 4] = rb[it];
            }
        }
        __syncthreads();
    }

    if (doStats) {
        #pragma unroll
        for (int j = 0; j < 4; ++j) {
            float s0 = 0.f, q0 = 0.f, s1 = 0.f, q1 = 0.f;
            #pragma unroll
            for (int i = 0; i < 2; ++i) {
                float v0 = c[i][j][0], v1 = c[i][j][1];
                float v2 = c[i][j][2], v3 = c[i][j][3];
                s0 += v0 + v2; q0 += v0 * v0 + v2 * v2;
                s1 += v1 + v3; q1 += v1 * v1 + v3 * v3;
            }
            #pragma unroll
            for (int m = 4; m < 32; m <<= 1) {
                s0 += __shfl_xor_sync(0xFFFFFFFFu, s0, m);
                q0 += __shfl_xor_sync(0xFFFFFFFFu, q0, m);
                s1 += __shfl_xor_sync(0xFFFFFFFFu, s1, m);
                q1 += __shfl_xor_sync(0xFFFFFFFFu, q1, m);
            }
            if (lane < 4) {
                int cc = col0 + wn + j * 8 + 2 * t;
                if (cc < EMB) {
                    atomicAdd(&g_stats[cc], s0);
                    atomicAdd(&g_stats[EMB + cc], q0);
                }
                if (cc + 1 < EMB) {
                    atomicAdd(&g_stats[cc + 1], s1);
                    atomicAdd(&g_stats[EMB + cc + 1], q1);
                }
            }
        }
        #pragma unroll
        for (int i = 0; i < 2; ++i) {
            int r = row0 + wm + i * 16 + g;
            #pragma unroll
            for (int j = 0; j < 4; ++j) {
                int cc = col0 + wn + j * 8 + 2 * t;
                if (cc >= N) continue;
                if (r < M)
                    *(float2*)&C[(size_t)r * N + cc] = make_float2(c[i][j][0], c[i][j][1]);
                int r2 = r + 8;
                if (r2 < M)
                    *(float2*)&C[(size_t)r2 * N + cc] = make_float2(c[i][j][2], c[i][j][3]);
            }
        }
    } else {
        #pragma unroll
        for (int i = 0; i < 2; ++i) {
            int r = row0 + wm + i * 16 + g;
            #pragma unroll
            for (int j = 0; j < 4; ++j) {
                int cc = col0 + wn + j * 8 + 2 * t;
                if (cc >= N) continue;
                float bx = bias[cc], by = bias[cc + 1];
                if (r < M) {
                    float2 v = make_float2(c[i][j][0] + bx, c[i][j][1] + by);
                    if (doRelu) { v.x = fmaxf(v.x, 0.f); v.y = fmaxf(v.y, 0.f); }
                    *(float2*)&C[(size_t)r * N + cc] = v;
                }
                int r2 = r + 8;
                if (r2 < M) {
                    float2 v = make_float2(c[i][j][2] + bx, c[i][j][3] + by);
                    if (doRelu) { v.x = fmaxf(v.x, 0.f); v.y = fmaxf(v.y, 0.f); }
                    *(float2*)&C[(size_t)r2 * N + cc] = v;
                }
            }
        }
    }
}

// -------- final-layer BN apply + pooled scatter (no relu) --------
__global__ void bn_pool_kernel(const float* __restrict__ X,
                               const float* __restrict__ gamma,
                               const float* __restrict__ beta,
                               const int* __restrict__ batch,
                               float* __restrict__ out, int l) {
    int idx = blockIdx.x * blockDim.x + threadIdx.x;
    if (idx >= N_NODES * EMB) return;
    int c = idx % EMB;
    float mu  = g_stats[c] * (1.f / N_NODES);
    float var = fmaxf(g_stats[EMB + c] * (1.f / N_NODES) - mu * mu, 0.f);
    float sc = rsqrtf(var + BN_EPS) * gamma[l * EMB + c];
    float v = (X[idx] - mu) * sc + beta[l * EMB + c];
    int i = idx / EMB;
    atomicAdd(&out[(size_t)batch[i] * EMB + c], v);
}

// ---------------- pooling ----------------
__global__ void pool_zero_kernel(float* __restrict__ out) {
    int idx = blockIdx.x * blockDim.x + threadIdx.x;
    if (idx < NUM_GRAPHS) g_counts[idx] = 0.f;
    if (idx < NUM_GRAPHS * EMB) out[idx] = 0.f;
}
__global__ void pool_count_kernel(const int* __restrict__ batch) {
    int i = blockIdx.x * blockDim.x + threadIdx.x;
    if (i >= N_NODES) return;
    atomicAdd(&g_counts[batch[i]], 1.f);
}
__global__ void pool_div_kernel(float* __restrict__ out) {
    int idx = blockIdx.x * blockDim.x + threadIdx.x;
    if (idx >= NUM_GRAPHS * EMB) return;
    out[idx] /= fmaxf(g_counts[idx / EMB], 1.f);
}

// ---------------- launch ----------------
extern "C" void kernel_launch(void* const* d_in, const int* in_sizes, int n_in,
                              void* d_out, int out_size) {
    const int*   x        = (const int*)d_in[0];
    const int*   edge_idx = (const int*)d_in[1];
    const int*   edge_att = (const int*)d_in[2];
    const int*   batch    = (const int*)d_in[3];
    const float* x_emb1   = (const float*)d_in[4];
    const float* x_emb2   = (const float*)d_in[5];
    const float* edge_e1  = (const float*)d_in[6];
    const float* edge_e2  = (const float*)d_in[7];
    const float* W1       = (const float*)d_in[8];
    const float* b1       = (const float*)d_in[9];
    const float* W2       = (const float*)d_in[10];
    const float* b2       = (const float*)d_in[11];
    const float* gamma    = (const float*)d_in[12];
    const float* beta     = (const float*)d_in[13];
    float* out = (float*)d_out;
    (void)b2;  // b2 cancels inside BatchNorm

    const int NE = N_NODES * EMB;
    const int TPB = 256;

    cudaFuncSetAttribute(gemm_n64_kernel,
                         cudaFuncAttributeMaxDynamicSharedMemorySize, GEMM_SMEM);

    init_h_kernel<<<(NE + TPB - 1) / TPB, TPB>>>(x, x_emb1, x_emb2);

    // ---- pre-split ALL layer weights (2 launches) ----
    __half *p_w1h, *p_w1l, *p_w2h, *p_w2l;
    cudaGetSymbolAddress((void**)&p_w1h, g_w1h);
    cudaGetSymbolAddress((void**)&p_w1l, g_w1l);
    cudaGetSymbolAddress((void**)&p_w2h, g_w2h);
    cudaGetSymbolAddress((void**)&p_w2l, g_w2l);
    dim3 tb(32, 8);
    dim3 tr1(640 / 32, 320 / 32, NUM_LAYER);   // W1: N=600->640, K=300->320
    dim3 tr2(384 / 32, 640 / 32, NUM_LAYER);   // W2: N=300->384, K=600->640
    transpose_split_all_kernel<<<tr1, tb>>>(W1, p_w1h, p_w1l, EMB2, EMB, 640, 320);
    transpose_split_all_kernel<<<tr2, tb>>>(W2, p_w2h, p_w2l, EMB, EMB2, 384, 640);

    // ---- build CSR once (graph constant across layers) ----
    const int NS = N_NODES + 1;
    const int SCAN_BLOCKS = (NS + 1023) / 1024;
    csr_zero_kernel<<<(NS + TPB - 1) / TPB, TPB>>>();
    csr_count_kernel<<<(N_EDGES + TPB - 1) / TPB, TPB>>>(edge_idx);
    csr_scan1_kernel<<<SCAN_BLOCKS, 1024>>>(NS);
    csr_scan2_kernel<<<1, 1024>>>(SCAN_BLOCKS);
    csr_scan3_kernel<<<SCAN_BLOCKS, 1024>>>(NS);
    csr_fill_kernel<<<(N_NODES + TPB - 1) / TPB, TPB>>>();
    csr_place_kernel<<<(N_EDGES + TPB - 1) / TPB, TPB>>>(edge_idx, edge_att);

    float *p_h, *p_agg, *p_t;
    cudaGetSymbolAddress((void**)&p_h, g_h);
    cudaGetSymbolAddress((void**)&p_agg, g_agg);
    cudaGetSymbolAddress((void**)&p_t, g_t);

    const int MT = (N_NODES + 127) / 128;
    dim3 gg1(10, MT);
    dim3 gg2(5, MT);

    for (int l = 0; l < NUM_LAYER; ++l) {
        // one prep kernel: bnco(l-1) from stats, zero stats, build tab(l)
        layer_prep_kernel<<<(9 * EMB + TPB - 1) / TPB, TPB>>>(edge_e1, edge_e2,
                                                              gamma, beta, l, l > 0);

        // gather: layer 0 reads g_h (init) -> g_agg; layers >=1 read g_agg (y)
        // with fused BN+relu -> g_h
        const float* gsrc = (l == 0) ? p_h : p_agg;
        float* gdst       = (l == 0) ? p_agg : p_h;
        gather_kernel<<<(N_NODES + 7) / 8, 256>>>(gsrc, gdst, l > 0);

        // t = relu(agg @ W1[l] + b1[l])   [N, 600]
        gemm_n64_kernel<<<gg1, 256, GEMM_SMEM>>>(gdst, p_w1h + (size_t)l * W1_LSZ,
                                                 p_w1l + (size_t)l * W1_LSZ,
                                                 b1 + l * EMB2, p_t,
                                                 N_NODES, EMB2, EMB, 320, 1, 0);
        // y = t @ W2[l]   [N, 300]  (bias cancels in BN; stats fused)
        gemm_n64_kernel<<<gg2, 256, GEMM_SMEM>>>(p_t, p_w2h + (size_t)l * W2_LSZ,
                                                 p_w2l + (size_t)l * W2_LSZ,
                                                 b2, p_agg,
                                                 N_NODES, EMB, EMB2, 640, 0, 1);
    }

    // final layer: BN apply (no relu) + mean pool
    pool_zero_kernel<<<(NUM_GRAPHS * EMB + TPB - 1) / TPB, TPB>>>(out);
    pool_count_kernel<<<(N_NODES + TPB - 1) / TPB, TPB>>>(batch);
    bn_pool_kernel<<<(NE + TPB - 1) / TPB, TPB>>>(p_agg, gamma, beta, batch, out,
                                                  NUM_LAYER - 1);
    pool_div_kernel<<<(NUM_GRAPHS * EMB + TPB - 1) / TPB, TPB>>>(out);
}